// round 4
// baseline (speedup 1.0000x reference)
#include <cuda_runtime.h>

#define NB 32
#define NS 1024
#define NE 4
#define NH 2
#define NF 16
#define NV 8
#define NTOK (NB*NS)

// scratch (no allocations allowed)
__device__ float g_x[NTOK * NE];     // residual stream
__device__ float g_qkv[NTOK * 12];   // q(4) k(4) v(4) per token

// ---------------------------------------------------------------------------
// Kernel 1: embedding gather + LN1 + QKV projection (layer given by pointers)
// ---------------------------------------------------------------------------
__global__ void embed_qkv_kernel(const int* __restrict__ tok,
                                 const float* __restrict__ emb,
                                 const float* __restrict__ ln_g,
                                 const float* __restrict__ ln_b,
                                 const float* __restrict__ wqkv)
{
    __shared__ float w[48], sg[4], sb[4];
    int t = threadIdx.x;
    if (t < 48) w[t] = wqkv[t];
    if (t < 4) { sg[t] = ln_g[t]; sb[t] = ln_b[t]; }
    __syncthreads();

    int i = blockIdx.x * blockDim.x + t;
    if (i >= NTOK) return;

    int tk = tok[i];
    float4 xv = *(const float4*)(emb + tk * 4);
    *(float4*)(g_x + i * 4) = xv;

    float mu = 0.25f * (xv.x + xv.y + xv.z + xv.w);
    float d0 = xv.x - mu, d1 = xv.y - mu, d2 = xv.z - mu, d3 = xv.w - mu;
    float var = 0.25f * (d0*d0 + d1*d1 + d2*d2 + d3*d3);
    float r = rsqrtf(var + 1e-5f);
    float h0 = d0*r*sg[0] + sb[0];
    float h1 = d1*r*sg[1] + sb[1];
    float h2 = d2*r*sg[2] + sb[2];
    float h3 = d3*r*sg[3] + sb[3];

    float q[12];
    #pragma unroll
    for (int f = 0; f < 12; f++)
        q[f] = fmaf(h0, w[4*f+0], fmaf(h1, w[4*f+1], fmaf(h2, w[4*f+2], h3 * w[4*f+3])));

    float4* qp = (float4*)(g_qkv + i * 12);
    qp[0] = make_float4(q[0], q[1], q[2],  q[3]);
    qp[1] = make_float4(q[4], q[5], q[6],  q[7]);
    qp[2] = make_float4(q[8], q[9], q[10], q[11]);
}

// ---------------------------------------------------------------------------
// Kernel 2: attention for one layer (+ Wo projection + residual add)
// grid = NB*8 blocks (8 query-chunks of 128 per batch), 128 threads/block.
// Full K/V for both heads of one batch lives in smem (32KB).
// ---------------------------------------------------------------------------
__global__ void attn_kernel(const float* __restrict__ wo)
{
    __shared__ float4 skv[NH][NS];   // (k0,k1,v0,v1) per key, per head
    __shared__ float swo[16];

    int b = blockIdx.x >> 3;
    int chunk = blockIdx.x & 7;
    int t = threadIdx.x;

    if (t < 16) swo[t] = wo[t];
    for (int idx = t; idx < NH * NS; idx += blockDim.x) {
        int h = idx >> 10;
        int j = idx & (NS - 1);
        const float* base = g_qkv + (size_t)(b * NS + j) * 12;
        float2 kk = *(const float2*)(base + 4 + 2*h);
        float2 vv = *(const float2*)(base + 8 + 2*h);
        skv[h][j] = make_float4(kk.x, kk.y, vv.x, vv.y);
    }
    __syncthreads();

    int i = b * NS + chunk * 128 + t;
    float4 qv = *(const float4*)(g_qkv + (size_t)i * 12);

    // fold 1/sqrt(D) and log2(e) into q so scores are directly exp2 exponents
    const float SC = 0.70710678118654752f * 1.4426950408889634f;
    float o[4];
    #pragma unroll
    for (int h = 0; h < 2; h++) {
        float q0 = (h ? qv.z : qv.x) * SC;
        float q1 = (h ? qv.w : qv.y) * SC;

        // pass 1: max
        float m = -1e30f;
        #pragma unroll 8
        for (int j = 0; j < NS; j++) {
            float4 kv = skv[h][j];
            float s = fmaf(q0, kv.x, q1 * kv.y);
            m = fmaxf(m, s);
        }
        // pass 2: exp + weighted accumulate
        float den = 0.f, a0 = 0.f, a1 = 0.f;
        #pragma unroll 8
        for (int j = 0; j < NS; j++) {
            float4 kv = skv[h][j];
            float s = fmaf(q0, kv.x, q1 * kv.y);
            float p = exp2f(s - m);
            den += p;
            a0 = fmaf(p, kv.z, a0);
            a1 = fmaf(p, kv.w, a1);
        }
        float inv = 1.0f / den;
        o[2*h]   = a0 * inv;
        o[2*h+1] = a1 * inv;
    }

    float4 xv = *(const float4*)(g_x + (size_t)i * 4);
    float x0 = xv.x, x1 = xv.y, x2 = xv.z, x3 = xv.w;
    float y0 = x0 + o[0]*swo[0]  + o[1]*swo[1]  + o[2]*swo[2]  + o[3]*swo[3];
    float y1 = x1 + o[0]*swo[4]  + o[1]*swo[5]  + o[2]*swo[6]  + o[3]*swo[7];
    float y2 = x2 + o[0]*swo[8]  + o[1]*swo[9]  + o[2]*swo[10] + o[3]*swo[11];
    float y3 = x3 + o[0]*swo[12] + o[1]*swo[13] + o[2]*swo[14] + o[3]*swo[15];
    *(float4*)(g_x + (size_t)i * 4) = make_float4(y0, y1, y2, y3);
}

// ---------------------------------------------------------------------------
// Kernel 3/5: FFN sublayer (+ residual). If !FINAL, fuse next layer's LN1+QKV.
// If FINAL, fuse the output projection to logits.
// ---------------------------------------------------------------------------
template<bool FINAL>
__global__ void ffn_kernel(const float* __restrict__ ln_g, const float* __restrict__ ln_b,
                           const float* __restrict__ w1, const float* __restrict__ b1,
                           const float* __restrict__ w2, const float* __restrict__ b2,
                           const float* __restrict__ ng, const float* __restrict__ nb,
                           const float* __restrict__ nwqkv,
                           const float* __restrict__ out_w, float* __restrict__ out)
{
    __shared__ float sw1[64], sb1[16], sw2[64], sb2[4], sg[4], sb[4];
    __shared__ float snw[48], sng[4], snb[4], sow[32];
    int t = threadIdx.x;
    if (t < 64) sw1[t] = w1[t];
    if (t >= 64 && t < 128) sw2[t - 64] = w2[t - 64];
    if (t < 16) sb1[t] = b1[t];
    if (t < 4) { sb2[t] = b2[t]; sg[t] = ln_g[t]; sb[t] = ln_b[t]; }
    if (FINAL) {
        if (t >= 128 && t < 160) sow[t - 128] = out_w[t - 128];
    } else {
        if (t >= 128 && t < 176) snw[t - 128] = nwqkv[t - 128];
        if (t >= 4 && t < 8)  sng[t - 4] = ng[t - 4];
        if (t >= 8 && t < 12) snb[t - 8] = nb[t - 8];
    }
    __syncthreads();

    int i = blockIdx.x * blockDim.x + t;
    if (i >= NTOK) return;

    float4 xv = *(const float4*)(g_x + (size_t)i * 4);
    float mu = 0.25f * (xv.x + xv.y + xv.z + xv.w);
    float d0 = xv.x - mu, d1 = xv.y - mu, d2 = xv.z - mu, d3 = xv.w - mu;
    float var = 0.25f * (d0*d0 + d1*d1 + d2*d2 + d3*d3);
    float r = rsqrtf(var + 1e-5f);
    float h0 = d0*r*sg[0] + sb[0];
    float h1 = d1*r*sg[1] + sb[1];
    float h2 = d2*r*sg[2] + sb[2];
    float h3 = d3*r*sg[3] + sb[3];

    float u[NF];
    #pragma unroll
    for (int f = 0; f < NF; f++) {
        float s = fmaf(h0, sw1[4*f+0], fmaf(h1, sw1[4*f+1],
                  fmaf(h2, sw1[4*f+2], fmaf(h3, sw1[4*f+3], sb1[f]))));
        u[f] = 0.5f * s * (1.0f + erff(s * 0.70710678118654752f));  // exact gelu
    }

    float y[4];
    #pragma unroll
    for (int e = 0; e < 4; e++) {
        float acc = sb2[e];
        #pragma unroll
        for (int f = 0; f < NF; f++) acc = fmaf(u[f], sw2[e*NF + f], acc);
        y[e] = acc;
    }
    y[0] += xv.x; y[1] += xv.y; y[2] += xv.z; y[3] += xv.w;

    if (FINAL) {
        float* op = out + (size_t)i * NV;
        #pragma unroll
        for (int v = 0; v < NV; v++)
            op[v] = fmaf(y[0], sow[4*v+0], fmaf(y[1], sow[4*v+1],
                    fmaf(y[2], sow[4*v+2], y[3] * sow[4*v+3])));
    } else {
        *(float4*)(g_x + (size_t)i * 4) = make_float4(y[0], y[1], y[2], y[3]);
        // next layer LN1 + QKV
        float mu2 = 0.25f * (y[0] + y[1] + y[2] + y[3]);
        float e0 = y[0]-mu2, e1 = y[1]-mu2, e2 = y[2]-mu2, e3 = y[3]-mu2;
        float var2 = 0.25f * (e0*e0 + e1*e1 + e2*e2 + e3*e3);
        float r2 = rsqrtf(var2 + 1e-5f);
        float g0 = e0*r2*sng[0] + snb[0];
        float g1 = e1*r2*sng[1] + snb[1];
        float g2 = e2*r2*sng[2] + snb[2];
        float g3 = e3*r2*sng[3] + snb[3];
        float q[12];
        #pragma unroll
        for (int f = 0; f < 12; f++)
            q[f] = fmaf(g0, snw[4*f+0], fmaf(g1, snw[4*f+1],
                   fmaf(g2, snw[4*f+2], g3 * snw[4*f+3])));
        float4* qp = (float4*)(g_qkv + (size_t)i * 12);
        qp[0] = make_float4(q[0], q[1], q[2],  q[3]);
        qp[1] = make_float4(q[4], q[5], q[6],  q[7]);
        qp[2] = make_float4(q[8], q[9], q[10], q[11]);
    }
}

// ---------------------------------------------------------------------------
extern "C" void kernel_launch(void* const* d_in, const int* in_sizes, int n_in,
                              void* d_out, int out_size)
{
    const int*   tok   = (const int*)  d_in[0];
    const float* emb   = (const float*)d_in[1];
    const float* ln1_g = (const float*)d_in[2];
    const float* ln1_b = (const float*)d_in[3];
    const float* wqkv  = (const float*)d_in[4];
    const float* wo    = (const float*)d_in[5];
    const float* ln2_g = (const float*)d_in[6];
    const float* ln2_b = (const float*)d_in[7];
    const float* w1    = (const float*)d_in[8];
    const float* b1    = (const float*)d_in[9];
    const float* w2    = (const float*)d_in[10];
    const float* b2    = (const float*)d_in[11];
    const float* out_w = (const float*)d_in[12];
    float* out = (float*)d_out;

    const int TB = 256;
    const int TG = (NTOK + TB - 1) / TB;   // 128 blocks

    // layer 0
    embed_qkv_kernel<<<TG, TB>>>(tok, emb, ln1_g, ln1_b, wqkv);
    attn_kernel<<<NB * 8, 128>>>(wo);
    // FFN(0) + LN1(1) + QKV(1)
    ffn_kernel<false><<<TG, TB>>>(ln2_g, ln2_b, w1, b1, w2, b2,
                                  ln1_g + NE, ln1_b + NE, wqkv + 48,
                                  nullptr, nullptr);
    // layer 1
    attn_kernel<<<NB * 8, 128>>>(wo + 16);
    // FFN(1) + output projection
    ffn_kernel<true><<<TG, TB>>>(ln2_g + NE, ln2_b + NE, w1 + 64, b1 + 16,
                                 w2 + 64, b2 + NE,
                                 nullptr, nullptr, nullptr, out_w, out);
}

// round 6
// speedup vs baseline: 3.0216x; 3.0216x over previous
#include <cuda_runtime.h>

#define NB 32
#define NS 1024
#define NE 4
#define NH 2
#define NF 16
#define NV 8
#define NTOK (NB*NS)

// scratch (no allocations allowed)
__device__ float g_x[NTOK * NE];     // residual stream
__device__ float g_qkv[NTOK * 12];   // q(4) k(4) v(4) per token

__device__ __forceinline__ float ex2(float x) {
    float y;
    asm("ex2.approx.ftz.f32 %0, %1;" : "=f"(y) : "f"(x));
    return y;
}

// ---------------------------------------------------------------------------
// Kernel 1: embedding gather + LN1 + QKV projection
// ---------------------------------------------------------------------------
__global__ void embed_qkv_kernel(const int* __restrict__ tok,
                                 const float* __restrict__ emb,
                                 const float* __restrict__ ln_g,
                                 const float* __restrict__ ln_b,
                                 const float* __restrict__ wqkv)
{
    __shared__ float w[48], sg[4], sb[4];
    int t = threadIdx.x;
    if (t < 48) w[t] = wqkv[t];
    if (t < 4) { sg[t] = ln_g[t]; sb[t] = ln_b[t]; }
    __syncthreads();

    int i = blockIdx.x * blockDim.x + t;
    if (i >= NTOK) return;

    int tk = tok[i];
    float4 xv = *(const float4*)(emb + tk * 4);
    *(float4*)(g_x + i * 4) = xv;

    float mu = 0.25f * (xv.x + xv.y + xv.z + xv.w);
    float d0 = xv.x - mu, d1 = xv.y - mu, d2 = xv.z - mu, d3 = xv.w - mu;
    float var = 0.25f * (d0*d0 + d1*d1 + d2*d2 + d3*d3);
    float r = rsqrtf(var + 1e-5f);
    float h0 = d0*r*sg[0] + sb[0];
    float h1 = d1*r*sg[1] + sb[1];
    float h2 = d2*r*sg[2] + sb[2];
    float h3 = d3*r*sg[3] + sb[3];

    float q[12];
    #pragma unroll
    for (int f = 0; f < 12; f++)
        q[f] = fmaf(h0, w[4*f+0], fmaf(h1, w[4*f+1], fmaf(h2, w[4*f+2], h3 * w[4*f+3])));

    float4* qp = (float4*)(g_qkv + i * 12);
    qp[0] = make_float4(q[0], q[1], q[2],  q[3]);
    qp[1] = make_float4(q[4], q[5], q[6],  q[7]);
    qp[2] = make_float4(q[8], q[9], q[10], q[11]);
}

// ---------------------------------------------------------------------------
// Kernel 2: attention (+ Wo projection + residual add), single-pass softmax.
// grid = NB*32 blocks: each block handles 32 queries of one batch.
// block = 256 threads = 32 queries x 8 key-splits (128 keys each).
// Full K/V for both heads of the batch lives in smem (32KB), interleaved so
// one LDS.128 per key serves both heads; all lanes broadcast (conflict-free).
// ---------------------------------------------------------------------------
__global__ void __launch_bounds__(256) attn_kernel(const float* __restrict__ wo)
{
    __shared__ float4 sk[NS];        // (k_h0_0, k_h0_1, k_h1_0, k_h1_1)
    __shared__ float4 sv[NS];        // (v_h0_0, v_h0_1, v_h1_0, v_h1_1)
    __shared__ float part[8][32][6]; // per-split partials
    __shared__ float swo[16];

    int b = blockIdx.x >> 5;
    int chunk = blockIdx.x & 31;
    int t = threadIdx.x;
    int qlocal = t & 31;
    int split = t >> 5;              // == warp id (32 lanes per split)

    if (t < 16) swo[t] = wo[t];
    #pragma unroll
    for (int j = t; j < NS; j += 256) {
        const float* base = g_qkv + (size_t)(b * NS + j) * 12;
        sk[j] = *(const float4*)(base + 4);
        sv[j] = *(const float4*)(base + 8);
    }
    __syncthreads();

    int i = b * NS + chunk * 32 + qlocal;
    float4 qv = *(const float4*)(g_qkv + (size_t)i * 12);

    // fold 1/sqrt(D) and log2(e) into q: scores become direct exp2 exponents.
    // No max-subtraction: |score| << 127 for this model, so exp2 can't overflow.
    const float SC = 0.70710678118654752f * 1.4426950408889634f;
    float q00 = qv.x * SC, q01 = qv.y * SC;
    float q10 = qv.z * SC, q11 = qv.w * SC;

    float den0 = 0.f, a00 = 0.f, a01 = 0.f;
    float den1 = 0.f, a10 = 0.f, a11 = 0.f;
    int j0 = split * 128;
    #pragma unroll 8
    for (int j = j0; j < j0 + 128; j++) {
        float4 kk = sk[j];
        float4 vv = sv[j];
        float p0 = ex2(fmaf(q00, kk.x, q01 * kk.y));
        float p1 = ex2(fmaf(q10, kk.z, q11 * kk.w));
        den0 += p0; a00 = fmaf(p0, vv.x, a00); a01 = fmaf(p0, vv.y, a01);
        den1 += p1; a10 = fmaf(p1, vv.z, a10); a11 = fmaf(p1, vv.w, a11);
    }
    float* pp = part[split][qlocal];
    pp[0] = den0; pp[1] = a00; pp[2] = a01;
    pp[3] = den1; pp[4] = a10; pp[5] = a11;
    __syncthreads();

    if (t < 32) {
        float r0 = 0.f, r1 = 0.f, r2 = 0.f, r3 = 0.f, r4 = 0.f, r5 = 0.f;
        #pragma unroll
        for (int s = 0; s < 8; s++) {
            const float* q = part[s][t];
            r0 += q[0]; r1 += q[1]; r2 += q[2];
            r3 += q[3]; r4 += q[4]; r5 += q[5];
        }
        float inv0 = 1.0f / r0, inv1 = 1.0f / r3;
        float o0 = r1 * inv0, o1 = r2 * inv0;
        float o2 = r4 * inv1, o3 = r5 * inv1;

        float4 xv = *(const float4*)(g_x + (size_t)i * 4);
        float y0 = xv.x + o0*swo[0]  + o1*swo[1]  + o2*swo[2]  + o3*swo[3];
        float y1 = xv.y + o0*swo[4]  + o1*swo[5]  + o2*swo[6]  + o3*swo[7];
        float y2 = xv.z + o0*swo[8]  + o1*swo[9]  + o2*swo[10] + o3*swo[11];
        float y3 = xv.w + o0*swo[12] + o1*swo[13] + o2*swo[14] + o3*swo[15];
        *(float4*)(g_x + (size_t)i * 4) = make_float4(y0, y1, y2, y3);
    }
}

// ---------------------------------------------------------------------------
// Kernel 3/5: FFN sublayer (+ residual). If !FINAL, fuse next layer's LN1+QKV.
// If FINAL, fuse the output projection to logits.
// ---------------------------------------------------------------------------
template<bool FINAL>
__global__ void ffn_kernel(const float* __restrict__ ln_g, const float* __restrict__ ln_b,
                           const float* __restrict__ w1, const float* __restrict__ b1,
                           const float* __restrict__ w2, const float* __restrict__ b2,
                           const float* __restrict__ ng, const float* __restrict__ nb,
                           const float* __restrict__ nwqkv,
                           const float* __restrict__ out_w, float* __restrict__ out)
{
    __shared__ float sw1[64], sb1[16], sw2[64], sb2[4], sg[4], sb[4];
    __shared__ float snw[48], sng[4], snb[4], sow[32];
    int t = threadIdx.x;
    if (t < 64) sw1[t] = w1[t];
    if (t >= 64 && t < 128) sw2[t - 64] = w2[t - 64];
    if (t < 16) sb1[t] = b1[t];
    if (t < 4) { sb2[t] = b2[t]; sg[t] = ln_g[t]; sb[t] = ln_b[t]; }
    if (FINAL) {
        if (t >= 128 && t < 160) sow[t - 128] = out_w[t - 128];
    } else {
        if (t >= 128 && t < 176) snw[t - 128] = nwqkv[t - 128];
        if (t >= 4 && t < 8)  sng[t - 4] = ng[t - 4];
        if (t >= 8 && t < 12) snb[t - 8] = nb[t - 8];
    }
    __syncthreads();

    int i = blockIdx.x * blockDim.x + t;
    if (i >= NTOK) return;

    float4 xv = *(const float4*)(g_x + (size_t)i * 4);
    float mu = 0.25f * (xv.x + xv.y + xv.z + xv.w);
    float d0 = xv.x - mu, d1 = xv.y - mu, d2 = xv.z - mu, d3 = xv.w - mu;
    float var = 0.25f * (d0*d0 + d1*d1 + d2*d2 + d3*d3);
    float r = rsqrtf(var + 1e-5f);
    float h0 = d0*r*sg[0] + sb[0];
    float h1 = d1*r*sg[1] + sb[1];
    float h2 = d2*r*sg[2] + sb[2];
    float h3 = d3*r*sg[3] + sb[3];

    float u[NF];
    #pragma unroll
    for (int f = 0; f < NF; f++) {
        float s = fmaf(h0, sw1[4*f+0], fmaf(h1, sw1[4*f+1],
                  fmaf(h2, sw1[4*f+2], fmaf(h3, sw1[4*f+3], sb1[f]))));
        u[f] = 0.5f * s * (1.0f + erff(s * 0.70710678118654752f));  // exact gelu
    }

    float y[4];
    #pragma unroll
    for (int e = 0; e < 4; e++) {
        float acc = sb2[e];
        #pragma unroll
        for (int f = 0; f < NF; f++) acc = fmaf(u[f], sw2[e*NF + f], acc);
        y[e] = acc;
    }
    y[0] += xv.x; y[1] += xv.y; y[2] += xv.z; y[3] += xv.w;

    if (FINAL) {
        float* op = out + (size_t)i * NV;
        #pragma unroll
        for (int v = 0; v < NV; v++)
            op[v] = fmaf(y[0], sow[4*v+0], fmaf(y[1], sow[4*v+1],
                    fmaf(y[2], sow[4*v+2], y[3] * sow[4*v+3])));
    } else {
        *(float4*)(g_x + (size_t)i * 4) = make_float4(y[0], y[1], y[2], y[3]);
        // next layer LN1 + QKV
        float mu2 = 0.25f * (y[0] + y[1] + y[2] + y[3]);
        float e0 = y[0]-mu2, e1 = y[1]-mu2, e2 = y[2]-mu2, e3 = y[3]-mu2;
        float var2 = 0.25f * (e0*e0 + e1*e1 + e2*e2 + e3*e3);
        float r2 = rsqrtf(var2 + 1e-5f);
        float g0 = e0*r2*sng[0] + snb[0];
        float g1 = e1*r2*sng[1] + snb[1];
        float g2 = e2*r2*sng[2] + snb[2];
        float g3 = e3*r2*sng[3] + snb[3];
        float q[12];
        #pragma unroll
        for (int f = 0; f < 12; f++)
            q[f] = fmaf(g0, snw[4*f+0], fmaf(g1, snw[4*f+1],
                   fmaf(g2, snw[4*f+2], g3 * snw[4*f+3])));
        float4* qp = (float4*)(g_qkv + (size_t)i * 12);
        qp[0] = make_float4(q[0], q[1], q[2],  q[3]);
        qp[1] = make_float4(q[4], q[5], q[6],  q[7]);
        qp[2] = make_float4(q[8], q[9], q[10], q[11]);
    }
}

// ---------------------------------------------------------------------------
extern "C" void kernel_launch(void* const* d_in, const int* in_sizes, int n_in,
                              void* d_out, int out_size)
{
    const int*   tok   = (const int*)  d_in[0];
    const float* emb   = (const float*)d_in[1];
    const float* ln1_g = (const float*)d_in[2];
    const float* ln1_b = (const float*)d_in[3];
    const float* wqkv  = (const float*)d_in[4];
    const float* wo    = (const float*)d_in[5];
    const float* ln2_g = (const float*)d_in[6];
    const float* ln2_b = (const float*)d_in[7];
    const float* w1    = (const float*)d_in[8];
    const float* b1    = (const float*)d_in[9];
    const float* w2    = (const float*)d_in[10];
    const float* b2    = (const float*)d_in[11];
    const float* out_w = (const float*)d_in[12];
    float* out = (float*)d_out;

    const int TB = 256;
    const int TG = (NTOK + TB - 1) / TB;   // 128 blocks

    // layer 0
    embed_qkv_kernel<<<TG, TB>>>(tok, emb, ln1_g, ln1_b, wqkv);
    attn_kernel<<<NB * 32, 256>>>(wo);
    // FFN(0) + LN1(1) + QKV(1)
    ffn_kernel<false><<<TG, TB>>>(ln2_g, ln2_b, w1, b1, w2, b2,
                                  ln1_g + NE, ln1_b + NE, wqkv + 48,
                                  nullptr, nullptr);
    // layer 1
    attn_kernel<<<NB * 32, 256>>>(wo + 16);
    // FFN(1) + output projection
    ffn_kernel<true><<<TG, TB>>>(ln2_g + NE, ln2_b + NE, w1 + 64, b1 + 16,
                                 w2 + 64, b2 + NE,
                                 nullptr, nullptr, nullptr, out_w, out);
}

// round 7
// speedup vs baseline: 3.2060x; 1.0610x over previous
#include <cuda_runtime.h>

#define NB 32
#define NS 1024
#define NE 4
#define NH 2
#define NF 16
#define NV 8
#define NTOK (NB*NS)

// scratch (no allocations allowed)
__device__ float g_x[NTOK * NE];     // residual stream
__device__ float g_qkv[NTOK * 12];   // q(4) k(4) v(4) per token

typedef unsigned long long ull;

__device__ __forceinline__ float ex2(float x) {
    float y;
    asm("ex2.approx.ftz.f32 %0, %1;" : "=f"(y) : "f"(x));
    return y;
}
__device__ __forceinline__ ull pk2(float a, float b) {
    ull r; asm("mov.b64 %0, {%1, %2};" : "=l"(r) : "f"(a), "f"(b)); return r;
}
__device__ __forceinline__ void upk2(ull v, float& a, float& b) {
    asm("mov.b64 {%0, %1}, %2;" : "=f"(a), "=f"(b) : "l"(v));
}
__device__ __forceinline__ ull fma2(ull a, ull b, ull c) {
    ull r; asm("fma.rn.f32x2 %0, %1, %2, %3;" : "=l"(r) : "l"(a), "l"(b), "l"(c)); return r;
}
__device__ __forceinline__ ull mul2(ull a, ull b) {
    ull r; asm("mul.rn.f32x2 %0, %1, %2;" : "=l"(r) : "l"(a), "l"(b)); return r;
}
__device__ __forceinline__ ull add2(ull a, ull b) {
    ull r; asm("add.rn.f32x2 %0, %1, %2;" : "=l"(r) : "l"(a), "l"(b)); return r;
}

// ---------------------------------------------------------------------------
// Kernel 1: embedding gather + LN1 + QKV projection
// ---------------------------------------------------------------------------
__global__ void embed_qkv_kernel(const int* __restrict__ tok,
                                 const float* __restrict__ emb,
                                 const float* __restrict__ ln_g,
                                 const float* __restrict__ ln_b,
                                 const float* __restrict__ wqkv)
{
    __shared__ float w[48], sg[4], sb[4];
    int t = threadIdx.x;
    if (t < 48) w[t] = wqkv[t];
    if (t < 4) { sg[t] = ln_g[t]; sb[t] = ln_b[t]; }
    __syncthreads();

    int i = blockIdx.x * blockDim.x + t;
    if (i >= NTOK) return;

    int tk = tok[i];
    float4 xv = *(const float4*)(emb + tk * 4);
    *(float4*)(g_x + i * 4) = xv;

    float mu = 0.25f * (xv.x + xv.y + xv.z + xv.w);
    float d0 = xv.x - mu, d1 = xv.y - mu, d2 = xv.z - mu, d3 = xv.w - mu;
    float var = 0.25f * (d0*d0 + d1*d1 + d2*d2 + d3*d3);
    float r = rsqrtf(var + 1e-5f);
    float h0 = d0*r*sg[0] + sb[0];
    float h1 = d1*r*sg[1] + sb[1];
    float h2 = d2*r*sg[2] + sb[2];
    float h3 = d3*r*sg[3] + sb[3];

    float q[12];
    #pragma unroll
    for (int f = 0; f < 12; f++)
        q[f] = fmaf(h0, w[4*f+0], fmaf(h1, w[4*f+1], fmaf(h2, w[4*f+2], h3 * w[4*f+3])));

    float4* qp = (float4*)(g_qkv + i * 12);
    qp[0] = make_float4(q[0], q[1], q[2],  q[3]);
    qp[1] = make_float4(q[4], q[5], q[6],  q[7]);
    qp[2] = make_float4(q[8], q[9], q[10], q[11]);
}

// ---------------------------------------------------------------------------
// Kernel 2: attention (+ Wo projection + residual add), single-pass softmax.
// grid = NB*32 blocks: each block handles 32 queries of one batch.
// block = 256 threads = 32 queries x 8 key-splits (128 keys each).
// Both heads processed in f32x2 packed lanes: smem K/V interleaved as
// (dim0_h0, dim0_h1, dim1_h0, dim1_h1) so LDS.128 register pairs feed
// fma.rn.f32x2 directly. MUFU (ex2) is the binding pipe (2 per key per warp).
// ---------------------------------------------------------------------------
__global__ void __launch_bounds__(256) attn_kernel(const float* __restrict__ wo)
{
    __shared__ float4 sk[NS];        // (k_d0_h0, k_d0_h1, k_d1_h0, k_d1_h1)
    __shared__ float4 sv[NS];        // (v_d0_h0, v_d0_h1, v_d1_h0, v_d1_h1)
    __shared__ float part[8][32][6]; // per-split partials
    __shared__ float swo[16];

    int b = blockIdx.x >> 5;
    int chunk = blockIdx.x & 31;
    int t = threadIdx.x;
    int qlocal = t & 31;
    int split = t >> 5;              // == warp id (32 lanes per split)

    if (t < 16) swo[t] = wo[t];
    #pragma unroll
    for (int j = t; j < NS; j += 256) {
        const float* base = g_qkv + (size_t)(b * NS + j) * 12;
        float4 kr = *(const float4*)(base + 4);  // (kh0d0, kh0d1, kh1d0, kh1d1)
        float4 vr = *(const float4*)(base + 8);
        sk[j] = make_float4(kr.x, kr.z, kr.y, kr.w);  // head-interleaved
        sv[j] = make_float4(vr.x, vr.z, vr.y, vr.w);
    }
    __syncthreads();

    int i = b * NS + chunk * 32 + qlocal;
    float4 qv = *(const float4*)(g_qkv + (size_t)i * 12);  // (qh0d0,qh0d1,qh1d0,qh1d1)

    // fold 1/sqrt(D) and log2(e) into q: scores become direct exp2 exponents.
    // No max-subtraction: |score| << 127 for this model, so exp2 can't overflow.
    const float SC = 0.70710678118654752f * 1.4426950408889634f;
    ull qd0 = pk2(qv.x * SC, qv.z * SC);   // dim-0 component, (h0, h1)
    ull qd1 = pk2(qv.y * SC, qv.w * SC);   // dim-1 component, (h0, h1)

    ull den = pk2(0.f, 0.f);               // (den_h0, den_h1)
    ull av0 = den, av1 = den;              // (a_h0_d, a_h1_d) for d=0,1
    int j0 = split * 128;
    #pragma unroll 8
    for (int j = j0; j < j0 + 128; j++) {
        float4 kk = sk[j];
        float4 vv = sv[j];
        ull kd0 = pk2(kk.x, kk.y);
        ull kd1 = pk2(kk.z, kk.w);
        ull s = fma2(qd0, kd0, mul2(qd1, kd1));   // (s_h0, s_h1)
        float s0, s1; upk2(s, s0, s1);
        ull p = pk2(ex2(s0), ex2(s1));            // (p_h0, p_h1)
        den = add2(den, p);
        av0 = fma2(p, pk2(vv.x, vv.y), av0);
        av1 = fma2(p, pk2(vv.z, vv.w), av1);
    }
    float d0, d1, a00, a10, a01, a11;
    upk2(den, d0, d1);     // den_h0, den_h1
    upk2(av0, a00, a10);   // a_h0_d0, a_h1_d0
    upk2(av1, a01, a11);   // a_h0_d1, a_h1_d1
    float* pp = part[split][qlocal];
    pp[0] = d0; pp[1] = a00; pp[2] = a01;
    pp[3] = d1; pp[4] = a10; pp[5] = a11;
    __syncthreads();

    if (t < 32) {
        float r0 = 0.f, r1 = 0.f, r2 = 0.f, r3 = 0.f, r4 = 0.f, r5 = 0.f;
        #pragma unroll
        for (int s = 0; s < 8; s++) {
            const float* q = part[s][t];
            r0 += q[0]; r1 += q[1]; r2 += q[2];
            r3 += q[3]; r4 += q[4]; r5 += q[5];
        }
        float inv0 = 1.0f / r0, inv1 = 1.0f / r3;
        float o0 = r1 * inv0, o1 = r2 * inv0;   // head0 dims
        float o2 = r4 * inv1, o3 = r5 * inv1;   // head1 dims

        float4 xv = *(const float4*)(g_x + (size_t)i * 4);
        float y0 = xv.x + o0*swo[0]  + o1*swo[1]  + o2*swo[2]  + o3*swo[3];
        float y1 = xv.y + o0*swo[4]  + o1*swo[5]  + o2*swo[6]  + o3*swo[7];
        float y2 = xv.z + o0*swo[8]  + o1*swo[9]  + o2*swo[10] + o3*swo[11];
        float y3 = xv.w + o0*swo[12] + o1*swo[13] + o2*swo[14] + o3*swo[15];
        *(float4*)(g_x + (size_t)i * 4) = make_float4(y0, y1, y2, y3);
    }
}

// ---------------------------------------------------------------------------
// Kernel 3/5: FFN sublayer (+ residual). If !FINAL, fuse next layer's LN1+QKV.
// If FINAL, fuse the output projection to logits.
// ---------------------------------------------------------------------------
template<bool FINAL>
__global__ void ffn_kernel(const float* __restrict__ ln_g, const float* __restrict__ ln_b,
                           const float* __restrict__ w1, const float* __restrict__ b1,
                           const float* __restrict__ w2, const float* __restrict__ b2,
                           const float* __restrict__ ng, const float* __restrict__ nb,
                           const float* __restrict__ nwqkv,
                           const float* __restrict__ out_w, float* __restrict__ out)
{
    __shared__ float sw1[64], sb1[16], sw2[64], sb2[4], sg[4], sb[4];
    __shared__ float snw[48], sng[4], snb[4], sow[32];
    int t = threadIdx.x;
    if (t < 64) sw1[t] = w1[t];
    if (t >= 64 && t < 128) sw2[t - 64] = w2[t - 64];
    if (t < 16) sb1[t] = b1[t];
    if (t < 4) { sb2[t] = b2[t]; sg[t] = ln_g[t]; sb[t] = ln_b[t]; }
    if (FINAL) {
        if (t >= 128 && t < 160) sow[t - 128] = out_w[t - 128];
    } else {
        if (t >= 128 && t < 176) snw[t - 128] = nwqkv[t - 128];
        if (t >= 4 && t < 8)  sng[t - 4] = ng[t - 4];
        if (t >= 8 && t < 12) snb[t - 8] = nb[t - 8];
    }
    __syncthreads();

    int i = blockIdx.x * blockDim.x + t;
    if (i >= NTOK) return;

    float4 xv = *(const float4*)(g_x + (size_t)i * 4);
    float mu = 0.25f * (xv.x + xv.y + xv.z + xv.w);
    float d0 = xv.x - mu, d1 = xv.y - mu, d2 = xv.z - mu, d3 = xv.w - mu;
    float var = 0.25f * (d0*d0 + d1*d1 + d2*d2 + d3*d3);
    float r = rsqrtf(var + 1e-5f);
    float h0 = d0*r*sg[0] + sb[0];
    float h1 = d1*r*sg[1] + sb[1];
    float h2 = d2*r*sg[2] + sb[2];
    float h3 = d3*r*sg[3] + sb[3];

    float u[NF];
    #pragma unroll
    for (int f = 0; f < NF; f++) {
        float s = fmaf(h0, sw1[4*f+0], fmaf(h1, sw1[4*f+1],
                  fmaf(h2, sw1[4*f+2], fmaf(h3, sw1[4*f+3], sb1[f]))));
        u[f] = 0.5f * s * (1.0f + erff(s * 0.70710678118654752f));  // exact gelu
    }

    float y[4];
    #pragma unroll
    for (int e = 0; e < 4; e++) {
        float acc = sb2[e];
        #pragma unroll
        for (int f = 0; f < NF; f++) acc = fmaf(u[f], sw2[e*NF + f], acc);
        y[e] = acc;
    }
    y[0] += xv.x; y[1] += xv.y; y[2] += xv.z; y[3] += xv.w;

    if (FINAL) {
        float* op = out + (size_t)i * NV;
        #pragma unroll
        for (int v = 0; v < NV; v++)
            op[v] = fmaf(y[0], sow[4*v+0], fmaf(y[1], sow[4*v+1],
                    fmaf(y[2], sow[4*v+2], y[3] * sow[4*v+3])));
    } else {
        *(float4*)(g_x + (size_t)i * 4) = make_float4(y[0], y[1], y[2], y[3]);
        // next layer LN1 + QKV
        float mu2 = 0.25f * (y[0] + y[1] + y[2] + y[3]);
        float e0 = y[0]-mu2, e1 = y[1]-mu2, e2 = y[2]-mu2, e3 = y[3]-mu2;
        float var2 = 0.25f * (e0*e0 + e1*e1 + e2*e2 + e3*e3);
        float r2 = rsqrtf(var2 + 1e-5f);
        float g0 = e0*r2*sng[0] + snb[0];
        float g1 = e1*r2*sng[1] + snb[1];
        float g2 = e2*r2*sng[2] + snb[2];
        float g3 = e3*r2*sng[3] + snb[3];
        float q[12];
        #pragma unroll
        for (int f = 0; f < 12; f++)
            q[f] = fmaf(g0, snw[4*f+0], fmaf(g1, snw[4*f+1],
                   fmaf(g2, snw[4*f+2], g3 * snw[4*f+3])));
        float4* qp = (float4*)(g_qkv + (size_t)i * 12);
        qp[0] = make_float4(q[0], q[1], q[2],  q[3]);
        qp[1] = make_float4(q[4], q[5], q[6],  q[7]);
        qp[2] = make_float4(q[8], q[9], q[10], q[11]);
    }
}

// ---------------------------------------------------------------------------
extern "C" void kernel_launch(void* const* d_in, const int* in_sizes, int n_in,
                              void* d_out, int out_size)
{
    const int*   tok   = (const int*)  d_in[0];
    const float* emb   = (const float*)d_in[1];
    const float* ln1_g = (const float*)d_in[2];
    const float* ln1_b = (const float*)d_in[3];
    const float* wqkv  = (const float*)d_in[4];
    const float* wo    = (const float*)d_in[5];
    const float* ln2_g = (const float*)d_in[6];
    const float* ln2_b = (const float*)d_in[7];
    const float* w1    = (const float*)d_in[8];
    const float* b1    = (const float*)d_in[9];
    const float* w2    = (const float*)d_in[10];
    const float* b2    = (const float*)d_in[11];
    const float* out_w = (const float*)d_in[12];
    float* out = (float*)d_out;

    const int TB = 256;
    const int TG = (NTOK + TB - 1) / TB;   // 128 blocks

    // layer 0
    embed_qkv_kernel<<<TG, TB>>>(tok, emb, ln1_g, ln1_b, wqkv);
    attn_kernel<<<NB * 32, 256>>>(wo);
    // FFN(0) + LN1(1) + QKV(1)
    ffn_kernel<false><<<TG, TB>>>(ln2_g, ln2_b, w1, b1, w2, b2,
                                  ln1_g + NE, ln1_b + NE, wqkv + 48,
                                  nullptr, nullptr);
    // layer 1
    attn_kernel<<<NB * 32, 256>>>(wo + 16);
    // FFN(1) + output projection
    ffn_kernel<true><<<TG, TB>>>(ln2_g + NE, ln2_b + NE, w1 + 64, b1 + 16,
                                 w2 + 64, b2 + NE,
                                 nullptr, nullptr, nullptr, out_w, out);
}

// round 8
// speedup vs baseline: 9.2437x; 2.8832x over previous
#include <cuda_runtime.h>

#define NB 32
#define NS 1024
#define NTOK (NB*NS)
#define NV 8

// per-(batch, token-id) logits table, filled by state_kernel
__device__ __align__(16) float g_logits[NB * 8 * NV];

__device__ __forceinline__ float ex2(float x) {
    float y;
    asm("ex2.approx.ftz.f32 %0, %1;" : "=f"(y) : "f"(x));
    return y;
}

// ---------------------------------------------------------------------------
// Kernel 1: one warp per batch. Computes the batch token histogram, then runs
// the ENTIRE 2-layer transformer for the 8 distinct per-batch token states
// (vocab=8, no positional encoding => tokens with equal id have equal state).
// Attention reduces to an 8-term histogram-weighted sum; K/V exchanged via
// __shfl (lanes 0-7 hold states 0-7; lanes 8-31 duplicate, keeping shfl trivial).
// ---------------------------------------------------------------------------
__global__ void __launch_bounds__(32) state_kernel(
    const int*   __restrict__ tok,
    const float* __restrict__ emb,
    const float* __restrict__ ln1_g, const float* __restrict__ ln1_b,
    const float* __restrict__ wqkv,  const float* __restrict__ wo,
    const float* __restrict__ ln2_g, const float* __restrict__ ln2_b,
    const float* __restrict__ w1,    const float* __restrict__ b1,
    const float* __restrict__ w2,    const float* __restrict__ b2,
    const float* __restrict__ out_w)
{
    const int b    = blockIdx.x;
    const int lane = threadIdx.x;
    const int id   = lane & 7;

    // ---- batch histogram (all 32 lanes cooperate, warp-reduced) ----
    int lc[8] = {0,0,0,0,0,0,0,0};
    const int* tb = tok + b * NS;
    #pragma unroll 4
    for (int j = lane; j < NS; j += 32) {
        int tk = tb[j];
        #pragma unroll
        for (int t = 0; t < 8; t++) lc[t] += (tk == t);
    }
    float cnt[8];
    #pragma unroll
    for (int t = 0; t < 8; t++) {
        int v = lc[t];
        #pragma unroll
        for (int o = 16; o; o >>= 1) v += __shfl_xor_sync(0xffffffffu, v, o);
        cnt[t] = (float)v;   // counts <= 1024: fp32-exact
    }

    // ---- initial state: embedding of this id ----
    float x0 = emb[id*4+0], x1 = emb[id*4+1], x2 = emb[id*4+2], x3 = emb[id*4+3];

    const float SC = 0.70710678118654752f * 1.4426950408889634f; // 1/sqrt(D)*log2(e)

    #pragma unroll
    for (int l = 0; l < 2; l++) {
        const float* G1  = ln1_g + l*4;  const float* B1  = ln1_b + l*4;
        const float* WQ  = wqkv  + l*48; const float* WO  = wo    + l*16;
        const float* G2  = ln2_g + l*4;  const float* B2n = ln2_b + l*4;
        const float* W1  = w1    + l*64; const float* Bf1 = b1    + l*16;
        const float* W2  = w2    + l*64; const float* Bf2 = b2    + l*4;

        // LN1
        float mu = 0.25f*(x0+x1+x2+x3);
        float d0 = x0-mu, d1 = x1-mu, d2 = x2-mu, d3 = x3-mu;
        float r  = rsqrtf(0.25f*(d0*d0+d1*d1+d2*d2+d3*d3) + 1e-5f);
        float h0 = d0*r*G1[0]+B1[0], h1 = d1*r*G1[1]+B1[1];
        float h2 = d2*r*G1[2]+B1[2], h3 = d3*r*G1[3]+B1[3];

        // QKV: rows 0-3 = q, 4-7 = k, 8-11 = v
        float qk[12];
        #pragma unroll
        for (int f = 0; f < 12; f++)
            qk[f] = fmaf(h0, WQ[4*f+0], fmaf(h1, WQ[4*f+1],
                    fmaf(h2, WQ[4*f+2], h3 * WQ[4*f+3])));

        float q00 = qk[0]*SC, q01 = qk[1]*SC;   // head0
        float q10 = qk[2]*SC, q11 = qk[3]*SC;   // head1

        // histogram-weighted softmax over the 8 distinct key states
        float den0 = 0.f, a00 = 0.f, a01 = 0.f;
        float den1 = 0.f, a10 = 0.f, a11 = 0.f;
        #pragma unroll
        for (int t = 0; t < 8; t++) {
            float k0 = __shfl_sync(0xffffffffu, qk[4],  t);
            float k1 = __shfl_sync(0xffffffffu, qk[5],  t);
            float k2 = __shfl_sync(0xffffffffu, qk[6],  t);
            float k3 = __shfl_sync(0xffffffffu, qk[7],  t);
            float v0 = __shfl_sync(0xffffffffu, qk[8],  t);
            float v1 = __shfl_sync(0xffffffffu, qk[9],  t);
            float v2 = __shfl_sync(0xffffffffu, qk[10], t);
            float v3 = __shfl_sync(0xffffffffu, qk[11], t);
            float wa = cnt[t] * ex2(fmaf(q00, k0, q01*k1));
            float wb = cnt[t] * ex2(fmaf(q10, k2, q11*k3));
            den0 += wa; a00 = fmaf(wa, v0, a00); a01 = fmaf(wa, v1, a01);
            den1 += wb; a10 = fmaf(wb, v2, a10); a11 = fmaf(wb, v3, a11);
        }
        float inv0 = 1.0f/den0, inv1 = 1.0f/den1;
        float o0 = a00*inv0, o1 = a01*inv0;     // head0 dims
        float o2 = a10*inv1, o3 = a11*inv1;     // head1 dims

        // Wo projection + residual
        float y0 = x0 + o0*WO[0]  + o1*WO[1]  + o2*WO[2]  + o3*WO[3];
        float y1 = x1 + o0*WO[4]  + o1*WO[5]  + o2*WO[6]  + o3*WO[7];
        float y2 = x2 + o0*WO[8]  + o1*WO[9]  + o2*WO[10] + o3*WO[11];
        float y3 = x3 + o0*WO[12] + o1*WO[13] + o2*WO[14] + o3*WO[15];

        // LN2 + FFN + residual
        mu = 0.25f*(y0+y1+y2+y3);
        d0 = y0-mu; d1 = y1-mu; d2 = y2-mu; d3 = y3-mu;
        r  = rsqrtf(0.25f*(d0*d0+d1*d1+d2*d2+d3*d3) + 1e-5f);
        h0 = d0*r*G2[0]+B2n[0]; h1 = d1*r*G2[1]+B2n[1];
        h2 = d2*r*G2[2]+B2n[2]; h3 = d3*r*G2[3]+B2n[3];

        float acc0 = Bf2[0], acc1 = Bf2[1], acc2 = Bf2[2], acc3 = Bf2[3];
        #pragma unroll
        for (int f = 0; f < 16; f++) {
            float s = fmaf(h0, W1[4*f+0], fmaf(h1, W1[4*f+1],
                      fmaf(h2, W1[4*f+2], fmaf(h3, W1[4*f+3], Bf1[f]))));
            float u = 0.5f * s * (1.0f + erff(s * 0.70710678118654752f)); // exact gelu
            acc0 = fmaf(u, W2[0*16+f], acc0);
            acc1 = fmaf(u, W2[1*16+f], acc1);
            acc2 = fmaf(u, W2[2*16+f], acc2);
            acc3 = fmaf(u, W2[3*16+f], acc3);
        }
        x0 = y0 + acc0; x1 = y1 + acc1; x2 = y2 + acc2; x3 = y3 + acc3;
    }

    // ---- final logits for this (batch, id) ----
    if (lane < 8) {
        float* op = g_logits + (b*8 + id) * NV;
        #pragma unroll
        for (int v = 0; v < NV; v++)
            op[v] = fmaf(x0, out_w[4*v+0], fmaf(x1, out_w[4*v+1],
                    fmaf(x2, out_w[4*v+2], x3 * out_w[4*v+3])));
    }
}

// ---------------------------------------------------------------------------
// Kernel 2: scatter the 256x8 logit table to the full [B,S,V] output.
// Pure memory: 128KB token reads + 1MB stores; table is L1/L2-resident.
// ---------------------------------------------------------------------------
__global__ void __launch_bounds__(256) scatter_kernel(const int* __restrict__ tok,
                                                      float* __restrict__ out)
{
    int i  = blockIdx.x * 256 + threadIdx.x;
    int b  = i >> 10;
    int id = tok[i];
    const float4* row = (const float4*)(g_logits + ((b << 3) + id) * NV);
    float4 r0 = row[0];
    float4 r1 = row[1];
    float4* op = (float4*)(out + (size_t)i * NV);
    op[0] = r0;
    op[1] = r1;
}

// ---------------------------------------------------------------------------
extern "C" void kernel_launch(void* const* d_in, const int* in_sizes, int n_in,
                              void* d_out, int out_size)
{
    const int*   tok   = (const int*)  d_in[0];
    const float* emb   = (const float*)d_in[1];
    const float* ln1_g = (const float*)d_in[2];
    const float* ln1_b = (const float*)d_in[3];
    const float* wqkv  = (const float*)d_in[4];
    const float* wo    = (const float*)d_in[5];
    const float* ln2_g = (const float*)d_in[6];
    const float* ln2_b = (const float*)d_in[7];
    const float* w1    = (const float*)d_in[8];
    const float* b1    = (const float*)d_in[9];
    const float* w2    = (const float*)d_in[10];
    const float* b2    = (const float*)d_in[11];
    const float* out_w = (const float*)d_in[12];
    float* out = (float*)d_out;

    state_kernel<<<NB, 32>>>(tok, emb, ln1_g, ln1_b, wqkv, wo,
                             ln2_g, ln2_b, w1, b1, w2, b2, out_w);
    scatter_kernel<<<NTOK / 256, 256>>>(tok, out);
}

// round 9
// speedup vs baseline: 11.9540x; 1.2932x over previous
#include <cuda_runtime.h>

#define NB 32
#define NS 1024
#define NTOK (NB*NS)
#define NV 8

typedef unsigned long long ull;

__device__ __forceinline__ float ex2(float x) {
    float y;
    asm("ex2.approx.ftz.f32 %0, %1;" : "=f"(y) : "f"(x));
    return y;
}

// ---------------------------------------------------------------------------
// ONE kernel, one block per batch (256 threads).
//   phase 1: all threads load 4 tokens each (kept in registers),
//            byte-packed histogram -> smem
//   phase 2: warp 0 runs the ENTIRE 2-layer transformer for the 8 distinct
//            per-batch token states (vocab=8, no positional encoding =>
//            equal ids have equal states; attention = histogram-weighted
//            8-term sum). Writes the 8x8 logit table to smem.
//   phase 3: all threads scatter the logit table to their 4 tokens
//            (contiguous 128B of STG.128 per thread).
// ---------------------------------------------------------------------------
__global__ void __launch_bounds__(256) fused_kernel(
    const int*   __restrict__ tok,
    const float* __restrict__ emb,
    const float* __restrict__ ln1_g, const float* __restrict__ ln1_b,
    const float* __restrict__ wqkv,  const float* __restrict__ wo,
    const float* __restrict__ ln2_g, const float* __restrict__ ln2_b,
    const float* __restrict__ w1,    const float* __restrict__ b1,
    const float* __restrict__ w2,    const float* __restrict__ b2,
    const float* __restrict__ out_w,
    float* __restrict__ out)
{
    __shared__ ull   whist[8];     // per-warp byte-packed histograms
    __shared__ float scnt[8];      // final per-bin counts (float)
    __shared__ __align__(16) float slog[8 * NV];  // 8 ids x 8 logits

    const int b    = blockIdx.x;
    const int t    = threadIdx.x;
    const int warp = t >> 5;
    const int lane = t & 31;

    // ---- phase 1: tokens (registers) + histogram ----
    int4 tk = ((const int4*)(tok + b * NS))[t];   // tokens 4t .. 4t+3
    ull c = (1ull << (8 * tk.x)) + (1ull << (8 * tk.y))
          + (1ull << (8 * tk.z)) + (1ull << (8 * tk.w));
    #pragma unroll
    for (int o = 16; o; o >>= 1) c += __shfl_xor_sync(0xffffffffu, c, o);
    if (lane == 0) whist[warp] = c;               // bins <=128/warp: no carry
    __syncthreads();

    if (t < 8) {                                  // thread t sums bin t
        float s = 0.f;
        #pragma unroll
        for (int w = 0; w < 8; w++) s += (float)((whist[w] >> (8 * t)) & 255u);
        scnt[t] = s;
    }
    __syncthreads();

    // ---- phase 2: warp 0 runs the network for the 8 distinct states ----
    if (warp == 0) {
        const int id = lane & 7;                  // lanes 8-31 duplicate
        float cw[8];
        #pragma unroll
        for (int i = 0; i < 8; i++) cw[i] = scnt[i];

        float x0 = emb[id*4+0], x1 = emb[id*4+1], x2 = emb[id*4+2], x3 = emb[id*4+3];
        const float SC = 0.70710678118654752f * 1.4426950408889634f;

        #pragma unroll
        for (int l = 0; l < 2; l++) {
            const float* G1  = ln1_g + l*4;  const float* B1  = ln1_b + l*4;
            const float* WQ  = wqkv  + l*48; const float* WO  = wo    + l*16;
            const float* G2  = ln2_g + l*4;  const float* B2n = ln2_b + l*4;
            const float* W1  = w1    + l*64; const float* Bf1 = b1    + l*16;
            const float* W2  = w2    + l*64; const float* Bf2 = b2    + l*4;

            // LN1
            float mu = 0.25f*(x0+x1+x2+x3);
            float d0 = x0-mu, d1 = x1-mu, d2 = x2-mu, d3 = x3-mu;
            float r  = rsqrtf(0.25f*(d0*d0+d1*d1+d2*d2+d3*d3) + 1e-5f);
            float h0 = d0*r*G1[0]+B1[0], h1 = d1*r*G1[1]+B1[1];
            float h2 = d2*r*G1[2]+B1[2], h3 = d3*r*G1[3]+B1[3];

            // QKV: rows 0-3 = q, 4-7 = k, 8-11 = v
            float qk[12];
            #pragma unroll
            for (int f = 0; f < 12; f++)
                qk[f] = fmaf(h0, WQ[4*f+0], fmaf(h1, WQ[4*f+1],
                        fmaf(h2, WQ[4*f+2], h3 * WQ[4*f+3])));

            float q00 = qk[0]*SC, q01 = qk[1]*SC;   // head0
            float q10 = qk[2]*SC, q11 = qk[3]*SC;   // head1

            // histogram-weighted softmax over the 8 distinct key states
            float den0 = 0.f, a00 = 0.f, a01 = 0.f;
            float den1 = 0.f, a10 = 0.f, a11 = 0.f;
            #pragma unroll
            for (int s = 0; s < 8; s++) {
                float k0 = __shfl_sync(0xffffffffu, qk[4],  s);
                float k1 = __shfl_sync(0xffffffffu, qk[5],  s);
                float k2 = __shfl_sync(0xffffffffu, qk[6],  s);
                float k3 = __shfl_sync(0xffffffffu, qk[7],  s);
                float v0 = __shfl_sync(0xffffffffu, qk[8],  s);
                float v1 = __shfl_sync(0xffffffffu, qk[9],  s);
                float v2 = __shfl_sync(0xffffffffu, qk[10], s);
                float v3 = __shfl_sync(0xffffffffu, qk[11], s);
                float wa = cw[s] * ex2(fmaf(q00, k0, q01*k1));
                float wb = cw[s] * ex2(fmaf(q10, k2, q11*k3));
                den0 += wa; a00 = fmaf(wa, v0, a00); a01 = fmaf(wa, v1, a01);
                den1 += wb; a10 = fmaf(wb, v2, a10); a11 = fmaf(wb, v3, a11);
            }
            float inv0 = 1.0f/den0, inv1 = 1.0f/den1;
            float o0 = a00*inv0, o1 = a01*inv0;
            float o2 = a10*inv1, o3 = a11*inv1;

            // Wo projection + residual
            float y0 = x0 + o0*WO[0]  + o1*WO[1]  + o2*WO[2]  + o3*WO[3];
            float y1 = x1 + o0*WO[4]  + o1*WO[5]  + o2*WO[6]  + o3*WO[7];
            float y2 = x2 + o0*WO[8]  + o1*WO[9]  + o2*WO[10] + o3*WO[11];
            float y3 = x3 + o0*WO[12] + o1*WO[13] + o2*WO[14] + o3*WO[15];

            // LN2 + FFN + residual
            mu = 0.25f*(y0+y1+y2+y3);
            d0 = y0-mu; d1 = y1-mu; d2 = y2-mu; d3 = y3-mu;
            r  = rsqrtf(0.25f*(d0*d0+d1*d1+d2*d2+d3*d3) + 1e-5f);
            h0 = d0*r*G2[0]+B2n[0]; h1 = d1*r*G2[1]+B2n[1];
            h2 = d2*r*G2[2]+B2n[2]; h3 = d3*r*G2[3]+B2n[3];

            float acc0 = Bf2[0], acc1 = Bf2[1], acc2 = Bf2[2], acc3 = Bf2[3];
            #pragma unroll
            for (int f = 0; f < 16; f++) {
                float s = fmaf(h0, W1[4*f+0], fmaf(h1, W1[4*f+1],
                          fmaf(h2, W1[4*f+2], fmaf(h3, W1[4*f+3], Bf1[f]))));
                float u = 0.5f * s * (1.0f + erff(s * 0.70710678118654752f));
                acc0 = fmaf(u, W2[0*16+f], acc0);
                acc1 = fmaf(u, W2[1*16+f], acc1);
                acc2 = fmaf(u, W2[2*16+f], acc2);
                acc3 = fmaf(u, W2[3*16+f], acc3);
            }
            x0 = y0 + acc0; x1 = y1 + acc1; x2 = y2 + acc2; x3 = y3 + acc3;
        }

        // final logits -> smem
        if (lane < 8) {
            float* op = slog + id * NV;
            #pragma unroll
            for (int v = 0; v < NV; v++)
                op[v] = fmaf(x0, out_w[4*v+0], fmaf(x1, out_w[4*v+1],
                        fmaf(x2, out_w[4*v+2], x3 * out_w[4*v+3])));
        }
    }
    __syncthreads();

    // ---- phase 3: scatter (4 tokens per thread, contiguous 128B) ----
    float4* op = (float4*)(out + ((size_t)b * NS + 4 * t) * NV);
    const float4* l0 = (const float4*)(slog + tk.x * NV);
    const float4* l1 = (const float4*)(slog + tk.y * NV);
    const float4* l2 = (const float4*)(slog + tk.z * NV);
    const float4* l3 = (const float4*)(slog + tk.w * NV);
    op[0] = l0[0]; op[1] = l0[1];
    op[2] = l1[0]; op[3] = l1[1];
    op[4] = l2[0]; op[5] = l2[1];
    op[6] = l3[0]; op[7] = l3[1];
}

// ---------------------------------------------------------------------------
extern "C" void kernel_launch(void* const* d_in, const int* in_sizes, int n_in,
                              void* d_out, int out_size)
{
    const int*   tok   = (const int*)  d_in[0];
    const float* emb   = (const float*)d_in[1];
    const float* ln1_g = (const float*)d_in[2];
    const float* ln1_b = (const float*)d_in[3];
    const float* wqkv  = (const float*)d_in[4];
    const float* wo    = (const float*)d_in[5];
    const float* ln2_g = (const float*)d_in[6];
    const float* ln2_b = (const float*)d_in[7];
    const float* w1    = (const float*)d_in[8];
    const float* b1    = (const float*)d_in[9];
    const float* w2    = (const float*)d_in[10];
    const float* b2    = (const float*)d_in[11];
    const float* out_w = (const float*)d_in[12];
    float* out = (float*)d_out;

    fused_kernel<<<NB, 256>>>(tok, emb, ln1_g, ln1_b, wqkv, wo,
                              ln2_g, ln2_b, w1, b1, w2, b2, out_w, out);
}

// round 10
// speedup vs baseline: 16.4548x; 1.3765x over previous
#include <cuda_runtime.h>

#define NB 32
#define NS 1024
#define NTOK (NB*NS)
#define NV 8

typedef unsigned long long ull;

// smem weight-table offsets (floats)
#define O_EMB   0     // 32
#define O_LN1G  32    // 8
#define O_LN1B  40    // 8
#define O_WQKV  48    // 96
#define O_WO    144   // 32
#define O_LN2G  176   // 8
#define O_LN2B  184   // 8
#define O_W1    192   // 128
#define O_B1    320   // 32
#define O_W2    352   // 128
#define O_B2    480   // 8
#define O_OUTW  488   // 32
#define W_TOTAL 520

__device__ __forceinline__ float ex2(float x) {
    float y;
    asm("ex2.approx.ftz.f32 %0, %1;" : "=f"(y) : "f"(x));
    return y;
}

// ---------------------------------------------------------------------------
// ONE kernel, one block per batch (256 threads).
//   phase 0: cooperative staging of ALL weights (520 floats) into smem,
//            issued alongside each thread's int4 token load -> one parallel
//            memory round-trip instead of ~30 serialized ones in warp 0.
//   phase 1: byte-packed warp histograms -> per-bin counts.
//   phase 2: warp 0 runs the entire 2-layer transformer for the 8 distinct
//            per-batch token states (vocab=8, no positional encoding =>
//            equal ids have equal states; attention = histogram-weighted
//            8-term sum), reading weights from smem (LDS).
//   phase 3: all threads scatter the 8x8 logit table (smem) to their
//            4 contiguous tokens (128B of STG.128 per thread).
// ---------------------------------------------------------------------------
__global__ void __launch_bounds__(256) fused_kernel(
    const int*   __restrict__ tok,
    const float* __restrict__ emb,
    const float* __restrict__ ln1_g, const float* __restrict__ ln1_b,
    const float* __restrict__ wqkv,  const float* __restrict__ wo,
    const float* __restrict__ ln2_g, const float* __restrict__ ln2_b,
    const float* __restrict__ w1,    const float* __restrict__ b1,
    const float* __restrict__ w2,    const float* __restrict__ b2,
    const float* __restrict__ out_w,
    float* __restrict__ out)
{
    __shared__ float sw[W_TOTAL];  // staged weights
    __shared__ ull   whist[8];     // per-warp byte-packed histograms
    __shared__ float scnt[8];      // final per-bin counts
    __shared__ __align__(16) float slog[8 * NV];  // 8 ids x 8 logits

    const int b    = blockIdx.x;
    const int t    = threadIdx.x;
    const int warp = t >> 5;
    const int lane = t & 31;

    // ---- phase 0: issue token load + weight staging (all parallel) ----
    int4 tk = ((const int4*)(tok + b * NS))[t];   // tokens 4t .. 4t+3

    #pragma unroll
    for (int idx = t; idx < W_TOTAL; idx += 256) {
        const float* src;
        int o = idx;
        if      (o < 32)  src = emb   + o;
        else if (o < 40)  src = ln1_g + (o - O_LN1G);
        else if (o < 48)  src = ln1_b + (o - O_LN1B);
        else if (o < 144) src = wqkv  + (o - O_WQKV);
        else if (o < 176) src = wo    + (o - O_WO);
        else if (o < 184) src = ln2_g + (o - O_LN2G);
        else if (o < 192) src = ln2_b + (o - O_LN2B);
        else if (o < 320) src = w1    + (o - O_W1);
        else if (o < 352) src = b1    + (o - O_B1);
        else if (o < 480) src = w2    + (o - O_W2);
        else if (o < 488) src = b2    + (o - O_B2);
        else              src = out_w + (o - O_OUTW);
        sw[idx] = *src;
    }

    // ---- phase 1: byte-packed histogram ----
    ull c = (1ull << (8 * tk.x)) + (1ull << (8 * tk.y))
          + (1ull << (8 * tk.z)) + (1ull << (8 * tk.w));
    #pragma unroll
    for (int o = 16; o; o >>= 1) c += __shfl_xor_sync(0xffffffffu, c, o);
    if (lane == 0) whist[warp] = c;               // bins <=128/warp: no carry
    __syncthreads();

    if (t < 8) {                                  // thread t sums bin t
        float s = 0.f;
        #pragma unroll
        for (int w = 0; w < 8; w++) s += (float)((whist[w] >> (8 * t)) & 255u);
        scnt[t] = s;
    }
    __syncthreads();

    // ---- phase 2: warp 0 runs the network for the 8 distinct states ----
    if (warp == 0) {
        const int id = lane & 7;                  // lanes 8-31 duplicate
        float cw[8];
        #pragma unroll
        for (int i = 0; i < 8; i++) cw[i] = scnt[i];

        float x0 = sw[O_EMB + id*4 + 0], x1 = sw[O_EMB + id*4 + 1];
        float x2 = sw[O_EMB + id*4 + 2], x3 = sw[O_EMB + id*4 + 3];
        const float SC = 0.70710678118654752f * 1.4426950408889634f;

        #pragma unroll
        for (int l = 0; l < 2; l++) {
            const float* G1  = sw + O_LN1G + l*4;  const float* B1  = sw + O_LN1B + l*4;
            const float* WQ  = sw + O_WQKV + l*48; const float* WO  = sw + O_WO   + l*16;
            const float* G2  = sw + O_LN2G + l*4;  const float* B2n = sw + O_LN2B + l*4;
            const float* W1  = sw + O_W1   + l*64; const float* Bf1 = sw + O_B1   + l*16;
            const float* W2  = sw + O_W2   + l*64; const float* Bf2 = sw + O_B2   + l*4;

            // LN1
            float mu = 0.25f*(x0+x1+x2+x3);
            float d0 = x0-mu, d1 = x1-mu, d2 = x2-mu, d3 = x3-mu;
            float r  = rsqrtf(0.25f*(d0*d0+d1*d1+d2*d2+d3*d3) + 1e-5f);
            float h0 = d0*r*G1[0]+B1[0], h1 = d1*r*G1[1]+B1[1];
            float h2 = d2*r*G1[2]+B1[2], h3 = d3*r*G1[3]+B1[3];

            // QKV: rows 0-3 = q, 4-7 = k, 8-11 = v
            float qk[12];
            #pragma unroll
            for (int f = 0; f < 12; f++)
                qk[f] = fmaf(h0, WQ[4*f+0], fmaf(h1, WQ[4*f+1],
                        fmaf(h2, WQ[4*f+2], h3 * WQ[4*f+3])));

            float q00 = qk[0]*SC, q01 = qk[1]*SC;   // head0
            float q10 = qk[2]*SC, q11 = qk[3]*SC;   // head1

            // histogram-weighted softmax over the 8 distinct key states
            float den0 = 0.f, a00 = 0.f, a01 = 0.f;
            float den1 = 0.f, a10 = 0.f, a11 = 0.f;
            #pragma unroll
            for (int s = 0; s < 8; s++) {
                float k0 = __shfl_sync(0xffffffffu, qk[4],  s);
                float k1 = __shfl_sync(0xffffffffu, qk[5],  s);
                float k2 = __shfl_sync(0xffffffffu, qk[6],  s);
                float k3 = __shfl_sync(0xffffffffu, qk[7],  s);
                float v0 = __shfl_sync(0xffffffffu, qk[8],  s);
                float v1 = __shfl_sync(0xffffffffu, qk[9],  s);
                float v2 = __shfl_sync(0xffffffffu, qk[10], s);
                float v3 = __shfl_sync(0xffffffffu, qk[11], s);
                float wa = cw[s] * ex2(fmaf(q00, k0, q01*k1));
                float wb = cw[s] * ex2(fmaf(q10, k2, q11*k3));
                den0 += wa; a00 = fmaf(wa, v0, a00); a01 = fmaf(wa, v1, a01);
                den1 += wb; a10 = fmaf(wb, v2, a10); a11 = fmaf(wb, v3, a11);
            }
            float inv0 = 1.0f/den0, inv1 = 1.0f/den1;
            float o0 = a00*inv0, o1 = a01*inv0;
            float o2 = a10*inv1, o3 = a11*inv1;

            // Wo projection + residual
            float y0 = x0 + o0*WO[0]  + o1*WO[1]  + o2*WO[2]  + o3*WO[3];
            float y1 = x1 + o0*WO[4]  + o1*WO[5]  + o2*WO[6]  + o3*WO[7];
            float y2 = x2 + o0*WO[8]  + o1*WO[9]  + o2*WO[10] + o3*WO[11];
            float y3 = x3 + o0*WO[12] + o1*WO[13] + o2*WO[14] + o3*WO[15];

            // LN2 + FFN + residual
            mu = 0.25f*(y0+y1+y2+y3);
            d0 = y0-mu; d1 = y1-mu; d2 = y2-mu; d3 = y3-mu;
            r  = rsqrtf(0.25f*(d0*d0+d1*d1+d2*d2+d3*d3) + 1e-5f);
            h0 = d0*r*G2[0]+B2n[0]; h1 = d1*r*G2[1]+B2n[1];
            h2 = d2*r*G2[2]+B2n[2]; h3 = d3*r*G2[3]+B2n[3];

            float acc0 = Bf2[0], acc1 = Bf2[1], acc2 = Bf2[2], acc3 = Bf2[3];
            #pragma unroll
            for (int f = 0; f < 16; f++) {
                float s = fmaf(h0, W1[4*f+0], fmaf(h1, W1[4*f+1],
                          fmaf(h2, W1[4*f+2], fmaf(h3, W1[4*f+3], Bf1[f]))));
                float u = 0.5f * s * (1.0f + erff(s * 0.70710678118654752f));
                acc0 = fmaf(u, W2[0*16+f], acc0);
                acc1 = fmaf(u, W2[1*16+f], acc1);
                acc2 = fmaf(u, W2[2*16+f], acc2);
                acc3 = fmaf(u, W2[3*16+f], acc3);
            }
            x0 = y0 + acc0; x1 = y1 + acc1; x2 = y2 + acc2; x3 = y3 + acc3;
        }

        // final logits -> smem
        if (lane < 8) {
            const float* OW = sw + O_OUTW;
            float* op = slog + id * NV;
            #pragma unroll
            for (int v = 0; v < NV; v++)
                op[v] = fmaf(x0, OW[4*v+0], fmaf(x1, OW[4*v+1],
                        fmaf(x2, OW[4*v+2], x3 * OW[4*v+3])));
        }
    }
    __syncthreads();

    // ---- phase 3: scatter (4 tokens per thread, contiguous 128B) ----
    float4* op = (float4*)(out + ((size_t)b * NS + 4 * t) * NV);
    const float4* l0 = (const float4*)(slog + tk.x * NV);
    const float4* l1 = (const float4*)(slog + tk.y * NV);
    const float4* l2 = (const float4*)(slog + tk.z * NV);
    const float4* l3 = (const float4*)(slog + tk.w * NV);
    op[0] = l0[0]; op[1] = l0[1];
    op[2] = l1[0]; op[3] = l1[1];
    op[4] = l2[0]; op[5] = l2[1];
    op[6] = l3[0]; op[7] = l3[1];
}

// ---------------------------------------------------------------------------
extern "C" void kernel_launch(void* const* d_in, const int* in_sizes, int n_in,
                              void* d_out, int out_size)
{
    const int*   tok   = (const int*)  d_in[0];
    const float* emb   = (const float*)d_in[1];
    const float* ln1_g = (const float*)d_in[2];
    const float* ln1_b = (const float*)d_in[3];
    const float* wqkv  = (const float*)d_in[4];
    const float* wo    = (const float*)d_in[5];
    const float* ln2_g = (const float*)d_in[6];
    const float* ln2_b = (const float*)d_in[7];
    const float* w1    = (const float*)d_in[8];
    const float* b1    = (const float*)d_in[9];
    const float* w2    = (const float*)d_in[10];
    const float* b2    = (const float*)d_in[11];
    const float* out_w = (const float*)d_in[12];
    float* out = (float*)d_out;

    fused_kernel<<<NB, 256>>>(tok, emb, ln1_g, ln1_b, wqkv, wo,
                              ln2_g, ln2_b, w1, b1, w2, b2, out_w, out);
}

// round 11
// speedup vs baseline: 20.1587x; 1.2251x over previous
#include <cuda_runtime.h>

#define NB 32
#define NS 1024
#define NTOK (NB*NS)
#define NV 8

typedef unsigned long long ull;

// smem weight-table offsets (floats)
#define O_EMB   0     // 32
#define O_LN1G  32    // 8
#define O_LN1B  40    // 8
#define O_WQKV  48    // 96
#define O_WO    144   // 32
#define O_LN2G  176   // 8
#define O_LN2B  184   // 8
#define O_W1    192   // 128
#define O_B1    320   // 32
#define O_W2    352   // 128
#define O_B2    480   // 8
#define O_OUTW  488   // 32
#define W_TOTAL 520

__device__ __forceinline__ float ex2(float x) {
    float y;
    asm("ex2.approx.ftz.f32 %0, %1;" : "=f"(y) : "f"(x));
    return y;
}

// ---------------------------------------------------------------------------
// ONE kernel, one block per batch (256 threads = 8 warps).
//   phase 0: token int4 load + cooperative weight staging into smem (parallel).
//   phase 1: byte-packed warp histograms -> per-bin counts.
//   phase 2: warp w runs the 2-layer network for distinct token-state w
//            (vocab=8, no positional encoding => equal ids share state;
//            attention = histogram-weighted 8-term sum). K/V exchanged via
//            smem (double-buffered per layer, 1 syncthreads each). The FFN is
//            lane-parallel: lane f computes ONE gelu/erff, butterfly-reduced.
//   phase 3: all threads scatter the 8x8 logit table to their 4 contiguous
//            tokens (128B of STG.128 per thread).
// ---------------------------------------------------------------------------
__global__ void __launch_bounds__(256) fused_kernel(
    const int*   __restrict__ tok,
    const float* __restrict__ emb,
    const float* __restrict__ ln1_g, const float* __restrict__ ln1_b,
    const float* __restrict__ wqkv,  const float* __restrict__ wo,
    const float* __restrict__ ln2_g, const float* __restrict__ ln2_b,
    const float* __restrict__ w1,    const float* __restrict__ b1,
    const float* __restrict__ w2,    const float* __restrict__ b2,
    const float* __restrict__ out_w,
    float* __restrict__ out)
{
    __shared__ float sw[W_TOTAL];                  // staged weights
    __shared__ ull   whist[8];                     // per-warp packed histograms
    __shared__ float scnt[8];                      // per-bin counts
    __shared__ __align__(16) float skv[2][8][8];   // [layer][state][k0..3 v0..3]
    __shared__ __align__(16) float slog[8 * NV];   // 8 ids x 8 logits

    const int b    = blockIdx.x;
    const int t    = threadIdx.x;
    const int warp = t >> 5;       // == state id this warp owns
    const int lane = t & 31;

    // ---- phase 0: token load + weight staging (one parallel round-trip) ----
    int4 tk = ((const int4*)(tok + b * NS))[t];    // tokens 4t .. 4t+3

    #pragma unroll
    for (int idx = t; idx < W_TOTAL; idx += 256) {
        const float* src;
        int o = idx;
        if      (o < 32)  src = emb   + o;
        else if (o < 40)  src = ln1_g + (o - O_LN1G);
        else if (o < 48)  src = ln1_b + (o - O_LN1B);
        else if (o < 144) src = wqkv  + (o - O_WQKV);
        else if (o < 176) src = wo    + (o - O_WO);
        else if (o < 184) src = ln2_g + (o - O_LN2G);
        else if (o < 192) src = ln2_b + (o - O_LN2B);
        else if (o < 320) src = w1    + (o - O_W1);
        else if (o < 352) src = b1    + (o - O_B1);
        else if (o < 480) src = w2    + (o - O_W2);
        else if (o < 488) src = b2    + (o - O_B2);
        else              src = out_w + (o - O_OUTW);
        sw[idx] = *src;
    }

    // ---- phase 1: byte-packed histogram ----
    ull c = (1ull << (8 * tk.x)) + (1ull << (8 * tk.y))
          + (1ull << (8 * tk.z)) + (1ull << (8 * tk.w));
    #pragma unroll
    for (int o = 16; o; o >>= 1) c += __shfl_xor_sync(0xffffffffu, c, o);
    if (lane == 0) whist[warp] = c;                // bins <=128/warp: no carry
    __syncthreads();

    if (t < 8) {                                   // thread t sums bin t
        float s = 0.f;
        #pragma unroll
        for (int w = 0; w < 8; w++) s += (float)((whist[w] >> (8 * t)) & 255u);
        scnt[t] = s;
    }
    __syncthreads();

    // ---- phase 2: warp w computes state w (all lanes replicate x) ----
    float cw[8];
    #pragma unroll
    for (int i = 0; i < 8; i++) cw[i] = scnt[i];

    float x0 = sw[O_EMB + warp*4 + 0], x1 = sw[O_EMB + warp*4 + 1];
    float x2 = sw[O_EMB + warp*4 + 2], x3 = sw[O_EMB + warp*4 + 3];
    const float SC = 0.70710678118654752f * 1.4426950408889634f;
    const int  fl  = lane & 15;                    // FFN hidden unit this lane owns

    #pragma unroll
    for (int l = 0; l < 2; l++) {
        const float* G1  = sw + O_LN1G + l*4;  const float* B1  = sw + O_LN1B + l*4;
        const float* WQ  = sw + O_WQKV + l*48; const float* WO  = sw + O_WO   + l*16;
        const float* G2  = sw + O_LN2G + l*4;  const float* B2n = sw + O_LN2B + l*4;
        const float* W1  = sw + O_W1   + l*64; const float* Bf1 = sw + O_B1   + l*16;
        const float* W2  = sw + O_W2   + l*64; const float* Bf2 = sw + O_B2   + l*4;

        // LN1 (replicated; cheap)
        float mu = 0.25f*(x0+x1+x2+x3);
        float d0 = x0-mu, d1 = x1-mu, d2 = x2-mu, d3 = x3-mu;
        float r  = rsqrtf(0.25f*(d0*d0+d1*d1+d2*d2+d3*d3) + 1e-5f);
        float h0 = d0*r*G1[0]+B1[0], h1 = d1*r*G1[1]+B1[1];
        float h2 = d2*r*G1[2]+B1[2], h3 = d3*r*G1[3]+B1[3];

        // QKV (replicated, 12 independent 4-term dots)
        float qk[12];
        #pragma unroll
        for (int f = 0; f < 12; f++)
            qk[f] = fmaf(h0, WQ[4*f+0], fmaf(h1, WQ[4*f+1],
                    fmaf(h2, WQ[4*f+2], h3 * WQ[4*f+3])));

        // publish this state's K and V
        if (lane == 0) {
            float4* dst = (float4*)skv[l][warp];
            dst[0] = make_float4(qk[4], qk[5], qk[6],  qk[7]);
            dst[1] = make_float4(qk[8], qk[9], qk[10], qk[11]);
        }
        __syncthreads();

        float q00 = qk[0]*SC, q01 = qk[1]*SC;      // head0
        float q10 = qk[2]*SC, q11 = qk[3]*SC;      // head1

        // histogram-weighted softmax over the 8 states (broadcast LDS reads)
        float den0 = 0.f, a00 = 0.f, a01 = 0.f;
        float den1 = 0.f, a10 = 0.f, a11 = 0.f;
        #pragma unroll
        for (int s = 0; s < 8; s++) {
            const float4* kv = (const float4*)skv[l][s];
            float4 k4 = kv[0];
            float4 v4 = kv[1];
            float wa = cw[s] * ex2(fmaf(q00, k4.x, q01*k4.y));
            float wb = cw[s] * ex2(fmaf(q10, k4.z, q11*k4.w));
            den0 += wa; a00 = fmaf(wa, v4.x, a00); a01 = fmaf(wa, v4.y, a01);
            den1 += wb; a10 = fmaf(wb, v4.z, a10); a11 = fmaf(wb, v4.w, a11);
        }
        float inv0 = 1.0f/den0, inv1 = 1.0f/den1;
        float o0 = a00*inv0, o1 = a01*inv0;
        float o2 = a10*inv1, o3 = a11*inv1;

        // Wo projection + residual (replicated)
        float y0 = x0 + o0*WO[0]  + o1*WO[1]  + o2*WO[2]  + o3*WO[3];
        float y1 = x1 + o0*WO[4]  + o1*WO[5]  + o2*WO[6]  + o3*WO[7];
        float y2 = x2 + o0*WO[8]  + o1*WO[9]  + o2*WO[10] + o3*WO[11];
        float y3 = x3 + o0*WO[12] + o1*WO[13] + o2*WO[14] + o3*WO[15];

        // LN2 (replicated)
        mu = 0.25f*(y0+y1+y2+y3);
        d0 = y0-mu; d1 = y1-mu; d2 = y2-mu; d3 = y3-mu;
        r  = rsqrtf(0.25f*(d0*d0+d1*d1+d2*d2+d3*d3) + 1e-5f);
        h0 = d0*r*G2[0]+B2n[0]; h1 = d1*r*G2[1]+B2n[1];
        h2 = d2*r*G2[2]+B2n[2]; h3 = d3*r*G2[3]+B2n[3];

        // FFN: lane-parallel. Lane handles hidden unit fl (lanes 16-31 mirror);
        // ONE gelu/erff per lane, then butterfly-reduce the 4 partial outputs.
        float s = fmaf(h0, W1[4*fl+0], fmaf(h1, W1[4*fl+1],
                  fmaf(h2, W1[4*fl+2], fmaf(h3, W1[4*fl+3], Bf1[fl]))));
        float u = 0.5f * s * (1.0f + erff(s * 0.70710678118654752f)); // exact gelu
        float p0 = u * W2[0*16+fl];
        float p1 = u * W2[1*16+fl];
        float p2 = u * W2[2*16+fl];
        float p3 = u * W2[3*16+fl];
        #pragma unroll
        for (int m = 8; m; m >>= 1) {              // reduce within 16-lane group
            p0 += __shfl_xor_sync(0xffffffffu, p0, m);
            p1 += __shfl_xor_sync(0xffffffffu, p1, m);
            p2 += __shfl_xor_sync(0xffffffffu, p2, m);
            p3 += __shfl_xor_sync(0xffffffffu, p3, m);
        }
        x0 = y0 + Bf2[0] + p0;
        x1 = y1 + Bf2[1] + p1;
        x2 = y2 + Bf2[2] + p2;
        x3 = y3 + Bf2[3] + p3;
    }

    // final logits: lane v computes logit v of state `warp`
    if (lane < 8) {
        const float* OW = sw + O_OUTW + 4*lane;
        slog[warp * NV + lane] =
            fmaf(x0, OW[0], fmaf(x1, OW[1], fmaf(x2, OW[2], x3 * OW[3])));
    }
    __syncthreads();

    // ---- phase 3: scatter (4 tokens per thread, contiguous 128B) ----
    float4* op = (float4*)(out + ((size_t)b * NS + 4 * t) * NV);
    const float4* l0 = (const float4*)(slog + tk.x * NV);
    const float4* l1 = (const float4*)(slog + tk.y * NV);
    const float4* l2 = (const float4*)(slog + tk.z * NV);
    const float4* l3 = (const float4*)(slog + tk.w * NV);
    op[0] = l0[0]; op[1] = l0[1];
    op[2] = l1[0]; op[3] = l1[1];
    op[4] = l2[0]; op[5] = l2[1];
    op[6] = l3[0]; op[7] = l3[1];
}

// ---------------------------------------------------------------------------
extern "C" void kernel_launch(void* const* d_in, const int* in_sizes, int n_in,
                              void* d_out, int out_size)
{
    const int*   tok   = (const int*)  d_in[0];
    const float* emb   = (const float*)d_in[1];
    const float* ln1_g = (const float*)d_in[2];
    const float* ln1_b = (const float*)d_in[3];
    const float* wqkv  = (const float*)d_in[4];
    const float* wo    = (const float*)d_in[5];
    const float* ln2_g = (const float*)d_in[6];
    const float* ln2_b = (const float*)d_in[7];
    const float* w1    = (const float*)d_in[8];
    const float* b1    = (const float*)d_in[9];
    const float* w2    = (const float*)d_in[10];
    const float* b2    = (const float*)d_in[11];
    const float* out_w = (const float*)d_in[12];
    float* out = (float*)d_out;

    fused_kernel<<<NB, 256>>>(tok, emb, ln1_g, ln1_b, wqkv, wo,
                              ln2_g, ln2_b, w1, b1, w2, b2, out_w, out);
}